// round 2
// baseline (speedup 1.0000x reference)
#include <cuda_runtime.h>
#include <cuda_bf16.h>

// BiLinearInteractionLayer: out[b, p, :] = (x[b,i_p,:] @ W) * x[b,j_p,:]
// x: [2048, 40, 64] fp32, W: [64, 64] fp32, out: [2048, 780*64] fp32.
// One CTA per batch row.
// Phase 1: stage x row-block + W in smem (vectorized).
// Phase 2: xw = x @ W, float4-register-tiled (1 LDS.128 of W reused 3x).
// Phase 3: i-grouped pair streaming — xw[i][d4] cached in a register across
//          all j>i, so exactly ONE LDS.128 per STG.128 (was two + LUT reads).

#define F_NUM   40
#define F_PAD   48          // padded rows: GEMM tile loop reads rows 40..47 (garbage, never stored)
#define EDIM    64
#define NPAIR   780         // F*(F-1)/2
#define TPB     256
#define BATCH_N 2048

__global__ __launch_bounds__(TPB, 4)
void bilinear_interact_kernel(const float* __restrict__ x,
                              const float* __restrict__ w,
                              float* __restrict__ out)
{
    __shared__ float sx [F_PAD * EDIM];   // 12 KB
    __shared__ float sxw[F_NUM * EDIM];   // 10 KB
    __shared__ float sw [EDIM * EDIM];    // 16 KB

    const int b   = blockIdx.x;
    const int tid = threadIdx.x;

    // ---- Phase 1: stage inputs ------------------------------------------
    {
        const float4* xg  = reinterpret_cast<const float4*>(x + (size_t)b * F_NUM * EDIM);
        float4*       sx4 = reinterpret_cast<float4*>(sx);
        #pragma unroll
        for (int t = tid; t < F_NUM * EDIM / 4; t += TPB) sx4[t] = xg[t];

        const float4* wg  = reinterpret_cast<const float4*>(w);
        float4*       sw4 = reinterpret_cast<float4*>(sw);
        #pragma unroll
        for (int t = tid; t < EDIM * EDIM / 4; t += TPB) sw4[t] = wg[t];
    }
    __syncthreads();

    // ---- Phase 2: xw = x @ W  (40x64 @ 64x64) ---------------------------
    // Thread owns one float4 column of W (col = tid&15) and 3 x-rows.
    {
        const int col   = tid & 15;    // float4 column (d/4)
        const int fbase = tid >> 4;    // 0..15
        const float4* swv  = reinterpret_cast<const float4*>(sw);
        float4*       sxw4 = reinterpret_cast<float4*>(sxw);

        float4 acc0 = make_float4(0.f, 0.f, 0.f, 0.f);
        float4 acc1 = acc0;
        float4 acc2 = acc0;

        #pragma unroll
        for (int k = 0; k < EDIM; k++) {
            const float4 wv = swv[k * 16 + col];
            const float a0 = sx[ fbase       * EDIM + k];
            const float a1 = sx[(fbase + 16) * EDIM + k];
            const float a2 = sx[(fbase + 32) * EDIM + k];  // padded-row read if fbase>=8
            acc0.x += a0 * wv.x; acc0.y += a0 * wv.y; acc0.z += a0 * wv.z; acc0.w += a0 * wv.w;
            acc1.x += a1 * wv.x; acc1.y += a1 * wv.y; acc1.z += a1 * wv.z; acc1.w += a1 * wv.w;
            acc2.x += a2 * wv.x; acc2.y += a2 * wv.y; acc2.z += a2 * wv.z; acc2.w += a2 * wv.w;
        }

        sxw4[ fbase       * 16 + col] = acc0;
        sxw4[(fbase + 16) * 16 + col] = acc1;
        if (fbase < 8)
            sxw4[(fbase + 32) * 16 + col] = acc2;
    }
    __syncthreads();

    // ---- Phase 3: i-grouped pair streaming ------------------------------
    // Thread: d4 = tid&15 (float4 lane), jg = tid>>4 (j offset group).
    // For each i: a = xw[i][d4] once (register), then stream j = i+1+jg, +16, ...
    // Warp stores: lanes 0-15 pair (pbase+jo), lanes 16-31 pair (pbase+jo+1)
    // -> contiguous 512B per warp store instruction.
    {
        const int d4 = tid & 15;
        const int jg = tid >> 4;
        float4*       out4 = reinterpret_cast<float4*>(out + (size_t)b * NPAIR * EDIM);
        const float4* sxc4 = reinterpret_cast<const float4*>(sx);
        const float4* sxw4 = reinterpret_cast<const float4*>(sxw);

        int pbase = 0;
        #pragma unroll 1
        for (int i = 0; i < F_NUM - 1; i++) {
            const float4 a  = sxw4[i * 16 + d4];
            const int    nj = F_NUM - 1 - i;
            #pragma unroll 3
            for (int jo = jg; jo < nj; jo += 16) {
                const int j = i + 1 + jo;
                const float4 v = sxc4[j * 16 + d4];
                const float4 r = make_float4(a.x * v.x, a.y * v.y, a.z * v.z, a.w * v.w);
                __stcs(&out4[(size_t)(pbase + jo) * 16 + d4], r);
            }
            pbase += nj;
        }
    }
}

extern "C" void kernel_launch(void* const* d_in, const int* in_sizes, int n_in,
                              void* d_out, int out_size)
{
    const float* x = (const float*)d_in[0];   // [2048, 40, 64]
    const float* w = (const float*)d_in[1];   // [64, 64]
    float* out = (float*)d_out;               // [2048, 780*64]
    (void)in_sizes; (void)n_in; (void)out_size;

    bilinear_interact_kernel<<<BATCH_N, TPB>>>(x, w, out);
}

// round 3
// speedup vs baseline: 1.0748x; 1.0748x over previous
#include <cuda_runtime.h>

// BiLinearInteractionLayer: out[b, p, :] = (x[b,i_p,:] @ W) * x[b,j_p,:]
// x: [2048, 40, 64] fp32, W: [64, 64] fp32, out: [2048, 780*64] fp32.
// One CTA per batch row.
// Phase 1: stage x (row-padded to 68 floats, bank-conflict-free) + W in smem.
// Phase 2: xw rows kept in REGISTERS: thread (col=tid&15, fb=tid>>4) computes
//          xw[{fb, 31-fb, 32+fb}][col float4] — balanced row set.
// Phase 3: stream pairs straight from the register accumulators: for each
//          owned i, loop j>i with ONE LDS.128 (x[j]) per STG.128. No sxw
//          smem, no a-reloads, no pair LUT.

#define F_NUM   40
#define EDIM    64
#define RPAD    68          // floats per sx row (17 float4) -> stride 4 mod 32 banks
#define RPAD4   17
#define NPAIR   780
#define TPB     256
#define BATCH_N 2048

__global__ __launch_bounds__(TPB, 5)
void bilinear_interact_kernel(const float* __restrict__ x,
                              const float* __restrict__ w,
                              float* __restrict__ out)
{
    __shared__ float sx[F_NUM * RPAD];    // 10.6 KB, padded rows
    __shared__ float sw[EDIM * EDIM];     // 16 KB

    const int b   = blockIdx.x;
    const int tid = threadIdx.x;

    // ---- Phase 1: stage inputs ------------------------------------------
    {
        const float4* xg  = reinterpret_cast<const float4*>(x + (size_t)b * F_NUM * EDIM);
        float4*       sx4 = reinterpret_cast<float4*>(sx);
        #pragma unroll
        for (int t = tid; t < F_NUM * EDIM / 4; t += TPB) {
            const int row = t >> 4;
            const int c   = t & 15;
            sx4[row * RPAD4 + c] = xg[t];
        }
        const float4* wg  = reinterpret_cast<const float4*>(w);
        float4*       sw4 = reinterpret_cast<float4*>(sw);
        #pragma unroll
        for (int t = tid; t < EDIM * EDIM / 4; t += TPB) sw4[t] = wg[t];
    }
    __syncthreads();

    const int col = tid & 15;   // float4 column of xw / out
    const int fb  = tid >> 4;   // 0..15

    // Balanced register row assignment (covers rows 0..39 exactly):
    const int i0 = fb;                          // 0..15
    const int i1 = 31 - fb;                     // 16..31
    const int i2 = (fb < 8) ? (32 + fb) : 39;   // 32..39 (fb>=8: row 39, nj=0)

    // ---- Phase 2: xw rows -> registers ----------------------------------
    float4 acc0 = make_float4(0.f, 0.f, 0.f, 0.f);
    float4 acc1 = acc0;
    float4 acc2 = acc0;
    {
        const float4* swv = reinterpret_cast<const float4*>(sw);
        #pragma unroll 8
        for (int k = 0; k < EDIM; k++) {
            const float4 wv = swv[k * 16 + col];
            const float a0 = sx[i0 * RPAD + k];
            const float a1 = sx[i1 * RPAD + k];
            const float a2 = sx[i2 * RPAD + k];
            acc0.x += a0 * wv.x; acc0.y += a0 * wv.y; acc0.z += a0 * wv.z; acc0.w += a0 * wv.w;
            acc1.x += a1 * wv.x; acc1.y += a1 * wv.y; acc1.z += a1 * wv.z; acc1.w += a1 * wv.w;
            acc2.x += a2 * wv.x; acc2.y += a2 * wv.y; acc2.z += a2 * wv.z; acc2.w += a2 * wv.w;
        }
    }
    // No sync needed: phase 3 reads sx (already sync'd) and registers only.

    // ---- Phase 3: stream pair products from registers --------------------
    // pb(i) = i*(79-i)/2 ; out[b, pb(i)+jo, :] = xw[i] * x[i+1+jo]
    {
        float4*       out4 = reinterpret_cast<float4*>(out + (size_t)b * NPAIR * EDIM);
        const float4* sx4  = reinterpret_cast<const float4*>(sx);

        #pragma unroll
        for (int r = 0; r < 3; r++) {
            const int    i = (r == 0) ? i0 : (r == 1) ? i1 : i2;
            const float4 a = (r == 0) ? acc0 : (r == 1) ? acc1 : acc2;
            const int    nj = F_NUM - 1 - i;
            const int    pb = (i * (2 * F_NUM - 1 - i)) >> 1;   // i*(79-i)/2
            float4* ob = out4 + (size_t)pb * 16 + col;
            const float4* vb = sx4 + (size_t)(i + 1) * RPAD4 + col;
            #pragma unroll 4
            for (int jo = 0; jo < nj; jo++) {
                const float4 v = vb[jo * RPAD4];
                const float4 p = make_float4(a.x * v.x, a.y * v.y, a.z * v.z, a.w * v.w);
                __stcs(ob + jo * 16, p);
            }
        }
    }
}

extern "C" void kernel_launch(void* const* d_in, const int* in_sizes, int n_in,
                              void* d_out, int out_size)
{
    const float* x = (const float*)d_in[0];   // [2048, 40, 64]
    const float* w = (const float*)d_in[1];   // [64, 64]
    float* out = (float*)d_out;               // [2048, 780*64]
    (void)in_sizes; (void)n_in; (void)out_size;

    bilinear_interact_kernel<<<BATCH_N, TPB>>>(x, w, out);
}